// round 4
// baseline (speedup 1.0000x reference)
#include <cuda_runtime.h>
#include <cstdint>

// ---------------------------------------------------------------------------
// Problem constants (static per reference)
// ---------------------------------------------------------------------------
#define BATCH 8
#define CIN   32
#define HH    96
#define WW    96
#define OCN   64
#define OHW   96
#define SSZ   (OHW*OHW)      // 9216
#define KK    (CIN*3*3)      // 288

// Output tile per block: 8 oh x 16 ow = 128 positions, all 64 oc.
// Block 256 threads: tx(16 ow) x ty(8 oc-octets) x tz(2 oh-halves).
#define TILE_H 8
#define TILE_W 16
#define PATCH_H (TILE_H + 2)   // 10
#define PATCH_W (TILE_W + 2)   // 18
#define PATCH_CH (PATCH_H * PATCH_W)  // 180
#define PATCH_SZ (CIN * PATCH_CH)     // 5760 float2 per array
#define SMEM_BYTES (2 * PATCH_SZ * 8) // u0d + u1d, duplicated floats: 92160 B

// Preprocessed slopes, k-major: d_S0[k][oc], d_S1[k][oc]
__device__ float d_S0[KK*OCN];
__device__ float d_S1[KK*OCN];
__device__ float d_bias[OCN];

// ---------------------------------------------------------------------------
// f32x2 packed helpers
// ---------------------------------------------------------------------------
__device__ __forceinline__ void fma2(uint64_t& d, uint64_t a, uint64_t b) {
    asm("fma.rn.f32x2 %0, %1, %2, %0;" : "+l"(d) : "l"(a), "l"(b));
}
__device__ __forceinline__ void unpack2(float& lo, float& hi, uint64_t v) {
    asm("mov.b64 {%0, %1}, %2;" : "=f"(lo), "=f"(hi) : "l"(v));
}

// ---------------------------------------------------------------------------
// Prep: per (oc,k) slopes + constant term.  grid(64), block(288)
// ---------------------------------------------------------------------------
__global__ void prep_w_kernel(const float* __restrict__ pos,
                              const float* __restrict__ val) {
    int oc = blockIdx.x;
    int k  = threadIdx.x;
    __shared__ float red[KK];

    const float* p = pos + ((size_t)(oc*KK + k))*3;
    const float* v = val + ((size_t)(oc*KK + k))*3;
    float p0 = p[0], p1 = p[1], p2 = p[2];
    float v0 = v[0], v1 = v[1], v2 = v[2];
    float dp0 = p1 - p0, dp1 = p2 - p1;
    float s0 = (dp0 > 0.f) ? (v1 - v0) / dp0 : 0.f;
    float s1 = (dp1 > 0.f) ? (v2 - v1) / dp1 : 0.f;

    d_S0[k*OCN + oc] = s0;
    d_S1[k*OCN + oc] = s1;
    red[k] = v0 - s0*p0 - s1*p1;
    __syncthreads();
    if (k == 0) {
        float s = 0.f;
        for (int i = 0; i < KK; i++) s += red[i];
        d_bias[oc] = s;
    }
}

// ---------------------------------------------------------------------------
// Main kernel: patch-resident implicit GEMM, packed f32x2 FMAs, with the
// clamped patch stored PRE-DUPLICATED (float2{v,v}) so every broadcast
// operand is a single LDS.64 — no pack movs. u values hoisted per column
// and reused across the 3 kh taps from registers.
// ---------------------------------------------------------------------------
__global__ __launch_bounds__(256, 2)
void pw_conv3_kernel(const float* __restrict__ x,
                     const float* __restrict__ pos,
                     float* __restrict__ out) {
    extern __shared__ float2 sm[];
    float2* u0d = sm;                 // [PATCH_SZ] duplicated clip(x,p0,p1)
    float2* u1d = sm + PATCH_SZ;      // [PATCH_SZ] duplicated clip(x,p1,p2)

    const int tid = threadIdx.x;
    const int tx  = tid & 15;          // ow within tile
    const int ty  = (tid >> 4) & 7;    // oc octet
    const int tz  = tid >> 7;          // oh half (0/1)

    const int b   = blockIdx.z;
    const int oh0 = blockIdx.y * TILE_H;
    const int ow0 = blockIdx.x * TILE_W;

    const float p0 = pos[0], p1 = pos[1], p2 = pos[2];

    // ---- Stage clamped, duplicated patch ----
    {
        const float* xb = x + (size_t)b * (CIN*HH*WW);
        for (int idx = tid; idx < PATCH_SZ; idx += 256) {
            int c = idx / PATCH_CH;
            int r = idx - c*PATCH_CH;
            int h = r / PATCH_W;
            int w = r - h*PATCH_W;
            int ih = oh0 - 1 + h;
            int iw = ow0 - 1 + w;
            float xv = 0.f;
            if ((unsigned)ih < HH && (unsigned)iw < WW)
                xv = xb[(c*HH + ih)*WW + iw];
            float a0 = fminf(fmaxf(xv, p0), p1);
            float a1 = fminf(fmaxf(xv, p1), p2);
            u0d[idx] = make_float2(a0, a0);
            u1d[idx] = make_float2(a1, a1);
        }
    }
    __syncthreads();

    // ---- Main loop ----
    // acc[j][pp]: j = oh sub-row (4 per thread), pp = oc pair (8 oc = 4 pairs)
    uint64_t acc[4][4];
#pragma unroll
    for (int j = 0; j < 4; j++)
#pragma unroll
        for (int pp = 0; pp < 4; pp++) acc[j][pp] = 0ull;

    const int rowbase = tz * 4;  // thread's first oh sub-row within the patch
    const float2* pu0 = u0d + rowbase * PATCH_W + tx;
    const float2* pu1 = u1d + rowbase * PATCH_W + tx;
    const float* pw0 = d_S0 + ty * 8;
    const float* pw1 = d_S1 + ty * 8;

    for (int c = 0; c < CIN; c++) {
#pragma unroll
        for (int kw = 0; kw < 3; kw++) {
            // hoist the 6 rows of this column (both terms), packed-dup'd
            uint64_t U0[6], U1[6];
#pragma unroll
            for (int r = 0; r < 6; r++) {
                U0[r] = *(const uint64_t*)(pu0 + r*PATCH_W + kw);
                U1[r] = *(const uint64_t*)(pu1 + r*PATCH_W + kw);
            }
#pragma unroll
            for (int kh = 0; kh < 3; kh++) {
                const int koff = (kh*3 + kw) * OCN;
                ulonglong2 w0a = *(const ulonglong2*)(pw0 + koff);
                ulonglong2 w0b = *(const ulonglong2*)(pw0 + koff + 4);
                ulonglong2 w1a = *(const ulonglong2*)(pw1 + koff);
                ulonglong2 w1b = *(const ulonglong2*)(pw1 + koff + 4);
#pragma unroll
                for (int j = 0; j < 4; j++) {
                    fma2(acc[j][0], U0[j + kh], w0a.x);
                    fma2(acc[j][1], U0[j + kh], w0a.y);
                    fma2(acc[j][2], U0[j + kh], w0b.x);
                    fma2(acc[j][3], U0[j + kh], w0b.y);
                    fma2(acc[j][0], U1[j + kh], w1a.x);
                    fma2(acc[j][1], U1[j + kh], w1a.y);
                    fma2(acc[j][2], U1[j + kh], w1b.x);
                    fma2(acc[j][3], U1[j + kh], w1b.y);
                }
            }
        }
        pu0 += PATCH_CH;
        pu1 += PATCH_CH;
        pw0 += 9 * OCN;
        pw1 += 9 * OCN;
    }

    // ---- Epilogue: unpack, add bias, store ----
    const int ocb = ty * 8;
    float bias[8];
#pragma unroll
    for (int i = 0; i < 8; i++) bias[i] = d_bias[ocb + i];

    float* ob = out + (size_t)b*OCN*SSZ + (size_t)ocb*SSZ
              + (size_t)(oh0 + rowbase)*OHW + (ow0 + tx);
#pragma unroll
    for (int j = 0; j < 4; j++) {
        float* orow = ob + (size_t)j*OHW;
#pragma unroll
        for (int pp = 0; pp < 4; pp++) {
            float lo, hi;
            unpack2(lo, hi, acc[j][pp]);
            orow[(size_t)(2*pp)    *SSZ] = lo + bias[2*pp];
            orow[(size_t)(2*pp + 1)*SSZ] = hi + bias[2*pp + 1];
        }
    }
}

// ---------------------------------------------------------------------------
extern "C" void kernel_launch(void* const* d_in, const int* in_sizes, int n_in,
                              void* d_out, int out_size) {
    const float* x   = (const float*)d_in[0];  // [8,32,96,96]
    const float* pos = (const float*)d_in[1];  // [64,32,3,3,3]
    const float* val = (const float*)d_in[2];  // [64,32,3,3,3]
    float* out = (float*)d_out;                // [8,64,96,96]

    cudaFuncSetAttribute(pw_conv3_kernel,
                         cudaFuncAttributeMaxDynamicSharedMemorySize,
                         SMEM_BYTES);

    prep_w_kernel<<<OCN, KK>>>(pos, val);
    dim3 grid(OHW / TILE_W, OHW / TILE_H, BATCH);
    pw_conv3_kernel<<<grid, 256, SMEM_BYTES>>>(x, pos, out);
}

// round 6
// speedup vs baseline: 2.3906x; 2.3906x over previous
#include <cuda_runtime.h>
#include <cuda_bf16.h>
#include <cstdint>

// ---------------------------------------------------------------------------
// Problem constants
// ---------------------------------------------------------------------------
#define BATCH 8
#define CIN   32
#define HH    96
#define WW    96
#define OCN   64
#define OHW   96
#define SSZ   (OHW*OHW)      // 9216
#define KK    (CIN*3*3)      // 288

#define TILE_H 8
#define TILE_W 16
#define PATCH_H 10
#define PATCH_W 18
#define NPIX    (PATCH_H*PATCH_W)    // 180

// Dynamic smem layout (bytes)
#define SM_WH     0                   // Wh: 9*64 rows x 128B = 73728
#define SM_WL     73728               // Wl: 73728
#define SM_PH     147456              // patch hi: 180 rows x 128B = 23040
#define SM_PL     170496              // patch lo: 23040
#define SM_SCR    193536              // fp32 scratch patch: 5760*4 = 23040
#define SM_BIAS   216576              // 64 floats
#define SM_TOTAL  216832

// Global preprocessed weights: [2 (hi/lo)][9 tap][64 oc][64 k] bf16
// k = cin (s0 slopes) | 32+cin (s1 slopes).  16B-aligned for uint4 staging.
__device__ __align__(16) __nv_bfloat16 g_W[2*9*64*64];
__device__ float g_bias[OCN];

// ---------------------------------------------------------------------------
// Prep: slopes -> bf16 hi/lo weight tiles + bias.  grid(64), block(288)
// ---------------------------------------------------------------------------
__global__ void prep_w_kernel(const float* __restrict__ pos,
                              const float* __restrict__ val) {
    int oc = blockIdx.x;
    int k  = threadIdx.x;              // cin*9 + tap
    __shared__ float red[KK];

    const float* p = pos + ((size_t)(oc*KK + k))*3;
    const float* v = val + ((size_t)(oc*KK + k))*3;
    float p0 = p[0], p1 = p[1], p2 = p[2];
    float v0 = v[0], v1 = v[1], v2 = v[2];
    float dp0 = p1 - p0, dp1 = p2 - p1;
    float s0 = (dp0 > 0.f) ? (v1 - v0) / dp0 : 0.f;
    float s1 = (dp1 > 0.f) ? (v2 - v1) / dp1 : 0.f;

    int cin = k / 9;
    int tap = k - cin*9;

    __nv_bfloat16 h0 = __float2bfloat16(s0);
    __nv_bfloat16 l0 = __float2bfloat16(s0 - __bfloat162float(h0));
    __nv_bfloat16 h1 = __float2bfloat16(s1);
    __nv_bfloat16 l1 = __float2bfloat16(s1 - __bfloat162float(h1));

    size_t rb = ((size_t)tap*64 + oc)*64;
    g_W[rb + cin]              = h0;
    g_W[rb + 32 + cin]         = h1;
    g_W[36864 + rb + cin]      = l0;
    g_W[36864 + rb + 32 + cin] = l1;

    red[k] = v0 - s0*p0 - s1*p1;
    __syncthreads();
    if (k == 0) {
        float s = 0.f;
        for (int i = 0; i < KK; i++) s += red[i];
        g_bias[oc] = s;
    }
}

// ---------------------------------------------------------------------------
// MMA helpers (baseline sm_80+ PTX — legal on plain sm_103)
// ---------------------------------------------------------------------------
__device__ __forceinline__ void ldsm4(uint32_t& r0, uint32_t& r1,
                                      uint32_t& r2, uint32_t& r3,
                                      uint32_t addr) {
    asm volatile("ldmatrix.sync.aligned.m8n8.x4.shared.b16 {%0,%1,%2,%3}, [%4];"
                 : "=r"(r0), "=r"(r1), "=r"(r2), "=r"(r3) : "r"(addr));
}
__device__ __forceinline__ void mma_bf16(float* d,
                                         uint32_t a0, uint32_t a1,
                                         uint32_t a2, uint32_t a3,
                                         uint32_t b0, uint32_t b1) {
    asm volatile(
        "mma.sync.aligned.m16n8k16.row.col.f32.bf16.bf16.f32 "
        "{%0,%1,%2,%3}, {%4,%5,%6,%7}, {%8,%9}, {%0,%1,%2,%3};"
        : "+f"(d[0]), "+f"(d[1]), "+f"(d[2]), "+f"(d[3])
        : "r"(a0), "r"(a1), "r"(a2), "r"(a3), "r"(b0), "r"(b1));
}
__device__ __forceinline__ uint32_t smem_u32(const void* p) {
    uint32_t a;
    asm("{ .reg .u64 t; cvta.to.shared.u64 t, %1; cvt.u32.u64 %0, t; }"
        : "=r"(a) : "l"(p));
    return a;
}
__device__ __forceinline__ uint32_t bf2_as_u32(__nv_bfloat162 v) {
    return reinterpret_cast<const uint32_t&>(v);   // align(4) type: safe
}

// ---------------------------------------------------------------------------
// Main: persistent blocks; each stages weights once, then loops over 4
// output tiles doing a 9-tap HMMA conv with split-bf16 error compensation.
// grid(144), block(256) = 8 warps; warp w owns oh-row w of the tile.
// ---------------------------------------------------------------------------
__global__ __launch_bounds__(256, 1)
void pw_mma_kernel(const float* __restrict__ x,
                   const float* __restrict__ pos,
                   float* __restrict__ out) {
    extern __shared__ char smem[];
    const uint32_t sb = smem_u32(smem);
    const int tid = threadIdx.x;
    const int l   = tid & 31;
    const int w   = tid >> 5;

    const float p0 = pos[0], p1 = pos[1], p2 = pos[2];

    // ---- Zero ALL dynamic smem (defensive: no byte read uninitialized) ----
    for (int i4 = tid; i4 < SM_TOTAL/16; i4 += 256)
        *(uint4*)(smem + (size_t)i4*16) = make_uint4(0u, 0u, 0u, 0u);
    __syncthreads();

    // ---- Stage all weights (hi+lo) into smem, XOR-swizzled 16B chunks ----
    {
        const uint4* gw = (const uint4*)g_W;
        for (int idx = tid; idx < 9216; idx += 256) {   // 1152 rows x 8 chunks
            int row = idx >> 3, kc = idx & 7;
            *(uint4*)(smem + row*128 + ((kc ^ (row & 7)) << 4)) = gw[idx];
        }
        if (tid < OCN)
            *(float*)(smem + SM_BIAS + tid*4) = g_bias[tid];
    }

    // lane constants
    const int rA     = l & 15;         // A fragment row (= ow_local)
    const int khalfA = l >> 4;
    const int ocb    = ((l >> 4) & 1)*8 + (l & 7);  // B lane oc offset
    const int khalfB = (l >> 3) & 1;
    const int bsw    = l & 7;

    // ---- Tile loop: 4 tiles per block ----
    for (int t = 0; t < 4; t++) {
        int tile = blockIdx.x*4 + t;
        int bb   = tile / 72;
        int rem  = tile - bb*72;
        int oh0  = (rem / 6) * TILE_H;
        int ow0  = (rem - (rem/6)*6) * TILE_W;

        __syncthreads();   // weight staging (t=0) / prior tile readers done

        // Phase A: fp32 patch -> scratch  (scr[c][p], p fastest)
        {
            const float* xb = x + (size_t)bb * (CIN*HH*WW);
            float* scr = (float*)(smem + SM_SCR);
            for (int idx = tid; idx < CIN*NPIX; idx += 256) {
                int c = idx / NPIX;
                int p = idx - c*NPIX;
                int h = p / PATCH_W;
                int ww2 = p - h*PATCH_W;
                int ih = oh0 - 1 + h;
                int iw = ow0 - 1 + ww2;
                float xv = 0.f;
                if ((unsigned)ih < HH && (unsigned)iw < WW)
                    xv = xb[(c*HH + ih)*WW + iw];
                scr[idx] = xv;
            }
        }
        __syncthreads();

        // Phase B: clamp + split -> swizzled bf16 patches (hi/lo).
        // Explicit bf16x2 register packing; no local-array casts.
        {
            const float* scr = (const float*)(smem + SM_SCR);
            for (int idx = tid; idx < NPIX*8; idx += 256) {  // 1440 chunks
                int p  = idx >> 3;
                int kc = idx & 7;
                uint32_t qh[4], ql[4];
#pragma unroll
                for (int jj = 0; jj < 4; jj++) {
                    int k0 = kc*8 + jj*2;
                    int cin0 = k0 & 31;
                    int cin1 = (k0 + 1) & 31;
                    float x0 = scr[cin0*NPIX + p];
                    float x1 = scr[cin1*NPIX + p];
                    float u0 = (k0     < 32) ? fminf(fmaxf(x0, p0), p1)
                                             : fminf(fmaxf(x0, p1), p2);
                    float u1 = (k0 + 1 < 32) ? fminf(fmaxf(x1, p0), p1)
                                             : fminf(fmaxf(x1, p1), p2);
                    __nv_bfloat162 h2 = __floats2bfloat162_rn(u0, u1);
                    float2 hf = __bfloat1622float2(h2);
                    __nv_bfloat162 l2 = __floats2bfloat162_rn(u0 - hf.x,
                                                              u1 - hf.y);
                    qh[jj] = bf2_as_u32(h2);
                    ql[jj] = bf2_as_u32(l2);
                }
                int off = p*128 + ((kc ^ (p & 7)) << 4);
                *(uint4*)(smem + SM_PH + off) = make_uint4(qh[0], qh[1],
                                                           qh[2], qh[3]);
                *(uint4*)(smem + SM_PL + off) = make_uint4(ql[0], ql[1],
                                                           ql[2], ql[3]);
            }
        }
        __syncthreads();

        // Phase C: 9-tap HMMA accumulation
        float acc[8][4];
#pragma unroll
        for (int nt = 0; nt < 8; nt++)
#pragma unroll
            for (int i = 0; i < 4; i++) acc[nt][i] = 0.f;

        for (int tap = 0; tap < 9; tap++) {
            int kh = tap / 3, kw = tap - (tap/3)*3;
            int pix  = (w + kh)*PATCH_W + rA + kw;     // this lane's A pixel
            uint32_t aoff = sb + pix*128;
            int psw = pix & 7;
            uint32_t boff = sb + (tap*64 + ocb)*128;   // lane's B row base

#pragma unroll
            for (int ks = 0; ks < 4; ks++) {
                int kcA = ks*2 + khalfA;
                uint32_t aaddr = aoff + ((kcA ^ psw) << 4);
                uint32_t ah0, ah1, ah2, ah3, al0, al1, al2, al3;
                ldsm4(ah0, ah1, ah2, ah3, aaddr + SM_PH);
                ldsm4(al0, al1, al2, al3, aaddr + SM_PL);

                int kcB = ks*2 + khalfB;
                uint32_t bh[16], bl[16];
#pragma unroll
                for (int i = 0; i < 4; i++) {
                    uint32_t baddr = boff + i*16*128 + ((kcB ^ bsw) << 4);
                    ldsm4(bh[4*i+0], bh[4*i+1], bh[4*i+2], bh[4*i+3],
                          baddr + SM_WH);
                    ldsm4(bl[4*i+0], bl[4*i+1], bl[4*i+2], bl[4*i+3],
                          baddr + SM_WL);
                }
#pragma unroll
                for (int nt = 0; nt < 8; nt++)
                    mma_bf16(acc[nt], ah0, ah1, ah2, ah3, bh[2*nt], bh[2*nt+1]);
#pragma unroll
                for (int nt = 0; nt < 8; nt++)
                    mma_bf16(acc[nt], ah0, ah1, ah2, ah3, bl[2*nt], bl[2*nt+1]);
#pragma unroll
                for (int nt = 0; nt < 8; nt++)
                    mma_bf16(acc[nt], al0, al1, al2, al3, bh[2*nt], bh[2*nt+1]);
            }
        }

        // Phase D: epilogue. Thread holds D rows (l>>2, l>>2+8), cols 2(l&3).
        {
            const float* bias = (const float*)(smem + SM_BIAS);
            int r0 = l >> 2;           // ow_local of c0/c1
            int cp = (l & 3) * 2;
            int oh = oh0 + w;
            size_t pbase = (size_t)bb*OCN*SSZ + (size_t)oh*OHW + ow0;
#pragma unroll
            for (int nt = 0; nt < 8; nt++) {
                int oc = nt*8 + cp;
                float b0 = bias[oc], b1 = bias[oc+1];
                float* o0 = out + pbase + (size_t)oc*SSZ;
                float* o1 = o0 + SSZ;
                o0[r0]     = acc[nt][0] + b0;
                o1[r0]     = acc[nt][1] + b1;
                o0[r0 + 8] = acc[nt][2] + b0;
                o1[r0 + 8] = acc[nt][3] + b1;
            }
        }
    }
}

// ---------------------------------------------------------------------------
extern "C" void kernel_launch(void* const* d_in, const int* in_sizes, int n_in,
                              void* d_out, int out_size) {
    const float* x   = (const float*)d_in[0];  // [8,32,96,96]
    const float* pos = (const float*)d_in[1];  // [64,32,3,3,3]
    const float* val = (const float*)d_in[2];  // [64,32,3,3,3]
    float* out = (float*)d_out;                // [8,64,96,96]

    cudaFuncSetAttribute(pw_mma_kernel,
                         cudaFuncAttributeMaxDynamicSharedMemorySize,
                         SM_TOTAL);

    prep_w_kernel<<<OCN, KK>>>(pos, val);
    pw_mma_kernel<<<144, 256, SM_TOTAL>>>(x, pos, out);
}